// round 2
// baseline (speedup 1.0000x reference)
#include <cuda_runtime.h>

#define DD 512
#define NB 8
#define NQ 128
#define NK 256

// Scratch for projected q/k (graph-capture safe: static device globals)
__device__ float g_qt[NB * NQ * DD];   // 2 MB
__device__ float g_kt[NB * NK * DD];   // 4 MB

__device__ __forceinline__ float fast_tanh(float x) {
    float y;
    asm("tanh.approx.f32 %0, %1;" : "=f"(y) : "f"(x));
    return y;
}

// ---------------------------------------------------------------------------
// Projection GEMM: C[m,n] = sum_k X[m,k] * W[n,k] + bias[n],  N = K = 512.
// Virtual M = 3072: rows [0,1024) -> q_t = query@W2^T + b2
//                   rows [1024,3072) -> k_t = key@W1^T + b1
// Tile 64x64, 128 threads, 8x4 micro-tile, K-chunk 32, k-major smem (+4 pad).
// ---------------------------------------------------------------------------
#define GM 64
#define GN 64
#define GKC 32

__global__ __launch_bounds__(128) void proj_kernel(
    const float* __restrict__ query, const float* __restrict__ key,
    const float* __restrict__ W1, const float* __restrict__ b1,
    const float* __restrict__ W2, const float* __restrict__ b2)
{
    __shared__ float Xs[GKC][GM + 4];
    __shared__ float Ws[GKC][GN + 4];

    const int m0 = blockIdx.x * GM;
    const int n0 = blockIdx.y * GN;

    const float *X, *W, *bias;
    float* out;
    if (m0 < NB * NQ) {
        X = query + m0 * DD; W = W2; bias = b2; out = g_qt + m0 * DD;
    } else {
        X = key + (m0 - NB * NQ) * DD; W = W1; bias = b1;
        out = g_kt + (m0 - NB * NQ) * DD;
    }

    const int tid = threadIdx.x;
    const int tx = tid & 15;   // col group (0..15), 4 cols each
    const int ty = tid >> 4;   // row group (0..7),  8 rows each

    float acc[8][4];
#pragma unroll
    for (int i = 0; i < 8; i++)
#pragma unroll
        for (int j = 0; j < 4; j++) acc[i][j] = 0.0f;

    for (int kc = 0; kc < DD; kc += GKC) {
        // Load X chunk (64x32) transposed into k-major smem: 4 float4/thread
#pragma unroll
        for (int i = 0; i < 4; i++) {
            int idx = tid + i * 128;            // 0..511
            int r = idx >> 3, fc = idx & 7;
            float4 t = *reinterpret_cast<const float4*>(&X[r * DD + kc + fc * 4]);
            Xs[fc * 4 + 0][r] = t.x; Xs[fc * 4 + 1][r] = t.y;
            Xs[fc * 4 + 2][r] = t.z; Xs[fc * 4 + 3][r] = t.w;
        }
        // Load W chunk (64x32) transposed
#pragma unroll
        for (int i = 0; i < 4; i++) {
            int idx = tid + i * 128;
            int r = idx >> 3, fc = idx & 7;
            float4 t = *reinterpret_cast<const float4*>(&W[(n0 + r) * DD + kc + fc * 4]);
            Ws[fc * 4 + 0][r] = t.x; Ws[fc * 4 + 1][r] = t.y;
            Ws[fc * 4 + 2][r] = t.z; Ws[fc * 4 + 3][r] = t.w;
        }
        __syncthreads();

#pragma unroll
        for (int kk = 0; kk < GKC; kk++) {
            float4 a0 = *reinterpret_cast<const float4*>(&Xs[kk][ty * 8]);
            float4 a1 = *reinterpret_cast<const float4*>(&Xs[kk][ty * 8 + 4]);
            float4 bw = *reinterpret_cast<const float4*>(&Ws[kk][tx * 4]);
            float xr[8] = {a0.x, a0.y, a0.z, a0.w, a1.x, a1.y, a1.z, a1.w};
            float wr[4] = {bw.x, bw.y, bw.z, bw.w};
#pragma unroll
            for (int i = 0; i < 8; i++)
#pragma unroll
                for (int j = 0; j < 4; j++)
                    acc[i][j] = fmaf(xr[i], wr[j], acc[i][j]);
        }
        __syncthreads();
    }

    float4 bb = *reinterpret_cast<const float4*>(&bias[n0 + tx * 4]);
#pragma unroll
    for (int i = 0; i < 8; i++) {
        float4 o;
        o.x = acc[i][0] + bb.x; o.y = acc[i][1] + bb.y;
        o.z = acc[i][2] + bb.z; o.w = acc[i][3] + bb.w;
        *reinterpret_cast<float4*>(&out[(ty * 8 + i) * DD + n0 + tx * 4]) = o;
    }
}

// ---------------------------------------------------------------------------
// Score kernel: scores[b,q,k] = sum_d v[d] * tanh(qt[b,q,d] + kt[b,k,d])
// Block tile: 32 q x 64 k, 256 threads, 2x4 register tile, D chunked by 64.
// MUFU(tanh)-bound by design: per d-step each warp issues 8 MUFU vs 16 FFMA.
// ---------------------------------------------------------------------------
#define SQ 32
#define SK 64
#define SD 64

__global__ __launch_bounds__(256) void score_kernel(
    const float* __restrict__ v, float* __restrict__ out)
{
    __shared__ float qs[SQ][SD + 1];
    __shared__ float ks[SK][SD + 1];
    __shared__ float vs[SD];

    const int b  = blockIdx.z;
    const int q0 = blockIdx.y * SQ;
    const int k0 = blockIdx.x * SK;
    const float* qt = g_qt + (b * NQ + q0) * DD;
    const float* kt = g_kt + (b * NK + k0) * DD;

    const int tid = threadIdx.x;
    const int tk = tid & 15;   // 4 k-cols each
    const int tq = tid >> 4;   // 2 q-rows each

    float acc[2][4] = {{0.f, 0.f, 0.f, 0.f}, {0.f, 0.f, 0.f, 0.f}};

    for (int dc = 0; dc < DD; dc += SD) {
        // qs: 32x64 floats = 512 float4, 2 per thread
#pragma unroll
        for (int i = 0; i < 2; i++) {
            int idx = tid + i * 256;
            int r = idx >> 4, fc = idx & 15;
            float4 t = *reinterpret_cast<const float4*>(&qt[r * DD + dc + fc * 4]);
            qs[r][fc * 4 + 0] = t.x; qs[r][fc * 4 + 1] = t.y;
            qs[r][fc * 4 + 2] = t.z; qs[r][fc * 4 + 3] = t.w;
        }
        // ks: 64x64 floats = 1024 float4, 4 per thread
#pragma unroll
        for (int i = 0; i < 4; i++) {
            int idx = tid + i * 256;
            int r = idx >> 4, fc = idx & 15;
            float4 t = *reinterpret_cast<const float4*>(&kt[r * DD + dc + fc * 4]);
            ks[r][fc * 4 + 0] = t.x; ks[r][fc * 4 + 1] = t.y;
            ks[r][fc * 4 + 2] = t.z; ks[r][fc * 4 + 3] = t.w;
        }
        if (tid < SD) vs[tid] = v[dc + tid];
        __syncthreads();

#pragma unroll 8
        for (int dd = 0; dd < SD; dd++) {
            float vq0 = qs[tq * 2 + 0][dd];
            float vq1 = qs[tq * 2 + 1][dd];
            float kv0 = ks[tk * 4 + 0][dd];
            float kv1 = ks[tk * 4 + 1][dd];
            float kv2 = ks[tk * 4 + 2][dd];
            float kv3 = ks[tk * 4 + 3][dd];
            float vd  = vs[dd];
            acc[0][0] = fmaf(vd, fast_tanh(vq0 + kv0), acc[0][0]);
            acc[0][1] = fmaf(vd, fast_tanh(vq0 + kv1), acc[0][1]);
            acc[0][2] = fmaf(vd, fast_tanh(vq0 + kv2), acc[0][2]);
            acc[0][3] = fmaf(vd, fast_tanh(vq0 + kv3), acc[0][3]);
            acc[1][0] = fmaf(vd, fast_tanh(vq1 + kv0), acc[1][0]);
            acc[1][1] = fmaf(vd, fast_tanh(vq1 + kv1), acc[1][1]);
            acc[1][2] = fmaf(vd, fast_tanh(vq1 + kv2), acc[1][2]);
            acc[1][3] = fmaf(vd, fast_tanh(vq1 + kv3), acc[1][3]);
        }
        __syncthreads();
    }

#pragma unroll
    for (int i = 0; i < 2; i++) {
        float4 o;
        o.x = acc[i][0]; o.y = acc[i][1]; o.z = acc[i][2]; o.w = acc[i][3];
        *reinterpret_cast<float4*>(
            &out[(b * NQ + q0 + tq * 2 + i) * NK + k0 + tk * 4]) = o;
    }
}

extern "C" void kernel_launch(void* const* d_in, const int* in_sizes, int n_in,
                              void* d_out, int out_size)
{
    const float* query = (const float*)d_in[0];  // [8,128,512]
    const float* key   = (const float*)d_in[1];  // [8,256,512]
    const float* W1    = (const float*)d_in[2];  // [512,512]
    const float* b1    = (const float*)d_in[3];  // [512]
    const float* W2    = (const float*)d_in[4];  // [512,512]
    const float* b2    = (const float*)d_in[5];  // [512]
    const float* v     = (const float*)d_in[6];  // [512]
    float* out = (float*)d_out;                  // [8,128,256]

    // Virtual M = 3072 rows (1024 q + 2048 k): 48 m-tiles x 8 n-tiles
    proj_kernel<<<dim3(48, 8), 128>>>(query, key, W1, b1, W2, b2);
    // 4 k-tiles x 4 q-tiles x 8 batches = 128 blocks
    score_kernel<<<dim3(NK / SK, NQ / SQ, NB), 256>>>(v, out);
}

// round 3
// speedup vs baseline: 1.1454x; 1.1454x over previous
#include <cuda_runtime.h>

#define DD 512
#define NB 8
#define NQ 128
#define NK 256
#define MQ (NB * NQ)            // 1024 query rows
#define MTOT (MQ + NB * NK)     // 3072 total rows

// ---------------------------------------------------------------------------
// Device scratch (graph-capture safe)
// ---------------------------------------------------------------------------
__device__ float g_qt[MQ * DD];          // projected queries  (2 MB)
__device__ float g_kt[NB * NK * DD];     // projected keys     (4 MB)
__device__ float g_xhi[MTOT * DD];       // tf32-hi of [query;key]
__device__ float g_xlo[MTOT * DD];       // tf32-lo residual
__device__ float g_whi[1024 * DD];       // rows 0-511: W2, 512-1023: W1
__device__ float g_wlo[1024 * DD];

__device__ __forceinline__ float fast_tanh(float x) {
    float y;
    asm("tanh.approx.f32 %0, %1;" : "=f"(y) : "f"(x));
    return y;
}

__device__ __forceinline__ void tf32_split(float x, float& hi, float& lo) {
    unsigned h, l;
    asm("cvt.rna.tf32.f32 %0, %1;" : "=r"(h) : "f"(x));
    float hf = __uint_as_float(h);
    float r = x - hf;
    asm("cvt.rna.tf32.f32 %0, %1;" : "=r"(l) : "f"(r));
    hi = hf;
    lo = __uint_as_float(l);
}

// ---------------------------------------------------------------------------
// Convert kernel: split all GEMM operands into tf32 hi/lo planes (once).
// 524288 float4s total: X(query 131072, key 262144), W2 65536, W1 65536.
// ---------------------------------------------------------------------------
__global__ __launch_bounds__(256) void convert_kernel(
    const float* __restrict__ query, const float* __restrict__ key,
    const float* __restrict__ W1, const float* __restrict__ W2)
{
    const int XQ4 = MQ * DD / 4;            // 131072
    const int XK4 = NB * NK * DD / 4;       // 262144
    const int W4  = 512 * DD / 4;           // 65536
    int gid = blockIdx.x * blockDim.x + threadIdx.x;   // 131072 threads
#pragma unroll
    for (int i = 0; i < 4; i++) {
        int idx = gid + i * 131072;
        const float4* src;
        float4 *dhi, *dlo;
        if (idx < XQ4) {
            src = (const float4*)query + idx;
            dhi = (float4*)g_xhi + idx;  dlo = (float4*)g_xlo + idx;
        } else if (idx < XQ4 + XK4) {
            src = (const float4*)key + (idx - XQ4);
            dhi = (float4*)g_xhi + idx;  dlo = (float4*)g_xlo + idx;
        } else if (idx < XQ4 + XK4 + W4) {
            int w = idx - (XQ4 + XK4);
            src = (const float4*)W2 + w;
            dhi = (float4*)g_whi + w;    dlo = (float4*)g_wlo + w;
        } else {
            int w = idx - (XQ4 + XK4 + W4);
            src = (const float4*)W1 + w;
            dhi = (float4*)g_whi + (W4 + w);  dlo = (float4*)g_wlo + (W4 + w);
        }
        float4 t = *src;
        float4 h, l;
        tf32_split(t.x, h.x, l.x);
        tf32_split(t.y, h.y, l.y);
        tf32_split(t.z, h.z, l.z);
        tf32_split(t.w, h.w, l.w);
        *dhi = h;
        *dlo = l;
    }
}

// ---------------------------------------------------------------------------
// Projection GEMM via tf32 mma.sync with 3-term compensation:
//   C = Xhi*Whi^T + Xlo*Whi^T + Xhi*Wlo^T  (+ bias)
// Block: 128 threads (4 warps, 2x2), tile 64m x 64n, k-chunk 32.
// Smem row stride 36 -> all fragment LDS patterns are (4r+c) mod 32: no conflicts.
// ---------------------------------------------------------------------------
#define PKC 32
#define PSTR 36

#define MMA_TF32(c, a, b0_, b1_)                                               \
    asm volatile(                                                              \
        "mma.sync.aligned.m16n8k8.row.col.f32.tf32.tf32.f32 "                  \
        "{%0,%1,%2,%3}, {%4,%5,%6,%7}, {%8,%9}, {%0,%1,%2,%3};"                \
        : "+f"((c)[0]), "+f"((c)[1]), "+f"((c)[2]), "+f"((c)[3])               \
        : "r"((a)[0]), "r"((a)[1]), "r"((a)[2]), "r"((a)[3]),                  \
          "r"(b0_), "r"(b1_))

__global__ __launch_bounds__(128) void proj_mma(
    const float* __restrict__ b1, const float* __restrict__ b2)
{
    __shared__ float Xh[64 * PSTR], Xl[64 * PSTR];
    __shared__ float Wh[64 * PSTR], Wl[64 * PSTR];

    const int m0 = blockIdx.x * 64;
    const int n0 = blockIdx.y * 64;
    const bool isQ = (m0 < MQ);
    const int wsel = isQ ? 0 : 512 * DD;
    const float* Xhg = g_xhi + m0 * DD;
    const float* Xlg = g_xlo + m0 * DD;
    const float* Whg = g_whi + wsel + n0 * DD;
    const float* Wlg = g_wlo + wsel + n0 * DD;
    const float* bias = isQ ? b2 : b1;
    float* out = isQ ? (g_qt + m0 * DD) : (g_kt + (m0 - MQ) * DD);

    const int tid = threadIdx.x;
    const int wid = tid >> 5, lane = tid & 31;
    const int mw = (wid & 1) * 32;    // warp m offset in tile
    const int nw = (wid >> 1) * 32;   // warp n offset in tile
    const int gr = lane >> 2;         // 0..7
    const int gc = lane & 3;          // 0..3

    float acc[2][4][4];
#pragma unroll
    for (int mf = 0; mf < 2; mf++)
#pragma unroll
        for (int nf = 0; nf < 4; nf++)
#pragma unroll
            for (int j = 0; j < 4; j++) acc[mf][nf][j] = 0.0f;

    for (int kc = 0; kc < DD; kc += PKC) {
#pragma unroll
        for (int i = 0; i < 4; i++) {
            int idx = tid + i * 128;           // 0..511
            int r = idx >> 3, c4 = (idx & 7) * 4;
            int so = r * PSTR + c4;
            int go = r * DD + kc + c4;
            *(float4*)&Xh[so] = *(const float4*)&Xhg[go];
            *(float4*)&Xl[so] = *(const float4*)&Xlg[go];
            *(float4*)&Wh[so] = *(const float4*)&Whg[go];
            *(float4*)&Wl[so] = *(const float4*)&Wlg[go];
        }
        __syncthreads();

#pragma unroll
        for (int s = 0; s < 4; s++) {
            const int k8 = s * 8;
            unsigned ah[2][4], al[2][4];
#pragma unroll
            for (int mf = 0; mf < 2; mf++) {
                int rb = (mw + mf * 16 + gr) * PSTR + k8 + gc;
                ah[mf][0] = __float_as_uint(Xh[rb]);
                ah[mf][1] = __float_as_uint(Xh[rb + 8 * PSTR]);
                ah[mf][2] = __float_as_uint(Xh[rb + 4]);
                ah[mf][3] = __float_as_uint(Xh[rb + 8 * PSTR + 4]);
                al[mf][0] = __float_as_uint(Xl[rb]);
                al[mf][1] = __float_as_uint(Xl[rb + 8 * PSTR]);
                al[mf][2] = __float_as_uint(Xl[rb + 4]);
                al[mf][3] = __float_as_uint(Xl[rb + 8 * PSTR + 4]);
            }
#pragma unroll
            for (int nf = 0; nf < 4; nf++) {
                int nb = (nw + nf * 8 + gr) * PSTR + k8 + gc;
                unsigned bh0 = __float_as_uint(Wh[nb]);
                unsigned bh1 = __float_as_uint(Wh[nb + 4]);
                unsigned bl0 = __float_as_uint(Wl[nb]);
                unsigned bl1 = __float_as_uint(Wl[nb + 4]);
#pragma unroll
                for (int mf = 0; mf < 2; mf++) {
                    MMA_TF32(acc[mf][nf], ah[mf], bh0, bh1);
                    MMA_TF32(acc[mf][nf], al[mf], bh0, bh1);
                    MMA_TF32(acc[mf][nf], ah[mf], bl0, bl1);
                }
            }
        }
        __syncthreads();
    }

    // Epilogue: C frags -> global, + bias
#pragma unroll
    for (int nf = 0; nf < 4; nf++) {
        int col = nw + nf * 8 + 2 * gc;                 // even
        float2 bb = *(const float2*)&bias[n0 + col];
#pragma unroll
        for (int mf = 0; mf < 2; mf++) {
            int row = mw + mf * 16 + gr;
            float2 o0, o1;
            o0.x = acc[mf][nf][0] + bb.x;  o0.y = acc[mf][nf][1] + bb.y;
            o1.x = acc[mf][nf][2] + bb.x;  o1.y = acc[mf][nf][3] + bb.y;
            *(float2*)&out[row * DD + n0 + col] = o0;
            *(float2*)&out[(row + 8) * DD + n0 + col] = o1;
        }
    }
}

// ---------------------------------------------------------------------------
// Score kernel: scores[b,q,k] = sum_d v[d] * tanh(qt[b,q,d] + kt[b,k,d])
// Tile 32q x 32k (256 blocks -> full SM coverage, ~2 resident/SM), 256 threads,
// 2x2 micro-tile. All smem loads conflict-free (stride-65 rows). MUFU-bound.
// ---------------------------------------------------------------------------
#define SQ 32
#define SK 32
#define SD 64

__global__ __launch_bounds__(256) void score_kernel(
    const float* __restrict__ v, float* __restrict__ out)
{
    __shared__ float qs[SQ][SD + 1];
    __shared__ float ks[SK][SD + 1];
    __shared__ float vs[SD];

    const int b  = blockIdx.z;
    const int q0 = blockIdx.y * SQ;
    const int k0 = blockIdx.x * SK;
    const float* qt = g_qt + (b * NQ + q0) * DD;
    const float* kt = g_kt + (b * NK + k0) * DD;

    const int tid = threadIdx.x;
    const int tk = tid & 15;    // 2 k each
    const int tq = tid >> 4;    // 2 q each

    float acc[2][2] = {{0.f, 0.f}, {0.f, 0.f}};

    for (int dc = 0; dc < DD; dc += SD) {
        // qs: 32x64 = 512 float4, 2 per thread
#pragma unroll
        for (int i = 0; i < 2; i++) {
            int idx = tid + i * 256;
            int r = idx >> 4, c4 = (idx & 15) * 4;
            float4 t = *(const float4*)&qt[r * DD + dc + c4];
            qs[r][c4] = t.x; qs[r][c4 + 1] = t.y;
            qs[r][c4 + 2] = t.z; qs[r][c4 + 3] = t.w;
        }
        // ks: 32x64 = 512 float4, 2 per thread
#pragma unroll
        for (int i = 0; i < 2; i++) {
            int idx = tid + i * 256;
            int r = idx >> 4, c4 = (idx & 15) * 4;
            float4 t = *(const float4*)&kt[r * DD + dc + c4];
            ks[r][c4] = t.x; ks[r][c4 + 1] = t.y;
            ks[r][c4 + 2] = t.z; ks[r][c4 + 3] = t.w;
        }
        if (tid < SD) vs[tid] = v[dc + tid];
        __syncthreads();

#pragma unroll 8
        for (int dd = 0; dd < SD; dd++) {
            float vq0 = qs[tq * 2 + 0][dd];
            float vq1 = qs[tq * 2 + 1][dd];
            float kv0 = ks[tk * 2 + 0][dd];
            float kv1 = ks[tk * 2 + 1][dd];
            float vd  = vs[dd];
            acc[0][0] = fmaf(vd, fast_tanh(vq0 + kv0), acc[0][0]);
            acc[0][1] = fmaf(vd, fast_tanh(vq0 + kv1), acc[0][1]);
            acc[1][0] = fmaf(vd, fast_tanh(vq1 + kv0), acc[1][0]);
            acc[1][1] = fmaf(vd, fast_tanh(vq1 + kv1), acc[1][1]);
        }
        __syncthreads();
    }

#pragma unroll
    for (int i = 0; i < 2; i++) {
        float2 o;
        o.x = acc[i][0]; o.y = acc[i][1];
        *(float2*)&out[(b * NQ + q0 + tq * 2 + i) * NK + k0 + tk * 2] = o;
    }
}

extern "C" void kernel_launch(void* const* d_in, const int* in_sizes, int n_in,
                              void* d_out, int out_size)
{
    const float* query = (const float*)d_in[0];  // [8,128,512]
    const float* key   = (const float*)d_in[1];  // [8,256,512]
    const float* W1    = (const float*)d_in[2];  // [512,512]
    const float* b1    = (const float*)d_in[3];  // [512]
    const float* W2    = (const float*)d_in[4];  // [512,512]
    const float* b2    = (const float*)d_in[5];  // [512]
    const float* v     = (const float*)d_in[6];  // [512]
    float* out = (float*)d_out;                  // [8,128,256]

    convert_kernel<<<512, 256>>>(query, key, W1, W2);
    // 48 m-tiles (3072/64) x 8 n-tiles (512/64)
    proj_mma<<<dim3(48, 8), 128>>>(b1, b2);
    // 8 k-tiles x 4 q-tiles x 8 batches = 256 blocks
    score_kernel<<<dim3(NK / SK, NQ / SQ, NB), 256>>>(v, out);
}

// round 4
// speedup vs baseline: 1.2240x; 1.0686x over previous
#include <cuda_runtime.h>
#include <cuda_bf16.h>
#include <cstdint>

#define DD 512
#define NB 8
#define NQ 128
#define NK 256
#define MQ (NB * NQ)            // 1024 query rows
#define MTOT (MQ + NB * NK)     // 3072 total rows

// ---------------------------------------------------------------------------
// Device scratch (graph-capture safe)
// ---------------------------------------------------------------------------
__device__ float g_qt[MQ * DD];               // projected queries (2 MB)
__device__ float g_kt[NB * NK * DD];          // projected keys    (4 MB)
__device__ __nv_bfloat16 g_xhi_bf[MTOT * DD]; // bf16-hi of [query;key]
__device__ __nv_bfloat16 g_xlo_bf[MTOT * DD]; // bf16-lo residual
__device__ __nv_bfloat16 g_whi_bf[1024 * DD]; // rows 0-511: W2, 512-1023: W1
__device__ __nv_bfloat16 g_wlo_bf[1024 * DD];

__device__ __forceinline__ float fast_tanh(float x) {
    float y;
    asm("tanh.approx.f32 %0, %1;" : "=f"(y) : "f"(x));
    return y;
}

__device__ __forceinline__ void bf16_split(float x, __nv_bfloat16& h, __nv_bfloat16& l) {
    h = __float2bfloat16_rn(x);
    l = __float2bfloat16_rn(x - __bfloat162float(h));
}

__device__ __forceinline__ void cp16(void* smem, const void* gmem) {
    unsigned s = (unsigned)__cvta_generic_to_shared(smem);
    asm volatile("cp.async.cg.shared.global [%0], [%1], 16;" :: "r"(s), "l"(gmem));
}
#define CP_COMMIT asm volatile("cp.async.commit_group;")
#define CP_WAIT1  asm volatile("cp.async.wait_group 1;")
#define CP_WAIT0  asm volatile("cp.async.wait_group 0;")

// ---------------------------------------------------------------------------
// Convert: split GEMM operands into bf16 hi/lo planes.
// 1024 blocks, each handles 512 float4 of exactly ONE segment (uniform branch):
//   blocks [0,256)   -> query   [256,768) -> key
//   blocks [768,896) -> W2      [896,1024) -> W1
// ---------------------------------------------------------------------------
__global__ __launch_bounds__(256) void convert_kernel(
    const float4* __restrict__ query, const float4* __restrict__ key,
    const float4* __restrict__ W1, const float4* __restrict__ W2)
{
    const int bi = blockIdx.x;
    const float4* src;
    __nv_bfloat16 *dh, *dl;
    int base;
    if (bi < 256) {
        src = query; dh = g_xhi_bf; dl = g_xlo_bf; base = bi * 512;
    } else if (bi < 768) {
        src = key; dh = g_xhi_bf + MQ * DD; dl = g_xlo_bf + MQ * DD;
        base = (bi - 256) * 512;
    } else if (bi < 896) {
        src = W2; dh = g_whi_bf; dl = g_wlo_bf; base = (bi - 768) * 512;
    } else {
        src = W1; dh = g_whi_bf + 512 * DD; dl = g_wlo_bf + 512 * DD;
        base = (bi - 896) * 512;
    }
#pragma unroll
    for (int i = 0; i < 2; i++) {
        int idx = base + threadIdx.x + i * 256;
        float4 t = src[idx];
        __nv_bfloat16 h[4], l[4];
        bf16_split(t.x, h[0], l[0]);
        bf16_split(t.y, h[1], l[1]);
        bf16_split(t.z, h[2], l[2]);
        bf16_split(t.w, h[3], l[3]);
        *(uint2*)&dh[(size_t)idx * 4] = *(uint2*)h;
        *(uint2*)&dl[(size_t)idx * 4] = *(uint2*)l;
    }
}

// ---------------------------------------------------------------------------
// Projection GEMM via bf16 mma.m16n8k16 with 3-term compensation:
//   C = Xhi*Whi^T + Xlo*Whi^T + Xhi*Wlo^T (+ bias)
// Block: 256 threads (8 warps, 4m x 2n grid, 32x32 warp tile),
// tile 128m x 64n, k-chunk 16, cp.async double-buffered.
// Smem rows stride 24 bf16 -> all fragment LDS.32 conflict-free.
// ---------------------------------------------------------------------------
#define BM 128
#define BN 64
#define PKC 16
#define XSTR 24

#define MMA_BF16(c, a, b0_, b1_)                                               \
    asm volatile(                                                              \
        "mma.sync.aligned.m16n8k16.row.col.f32.bf16.bf16.f32 "                 \
        "{%0,%1,%2,%3}, {%4,%5,%6,%7}, {%8,%9}, {%0,%1,%2,%3};"                \
        : "+f"((c)[0]), "+f"((c)[1]), "+f"((c)[2]), "+f"((c)[3])               \
        : "r"((a)[0]), "r"((a)[1]), "r"((a)[2]), "r"((a)[3]),                  \
          "r"(b0_), "r"(b1_))

__global__ __launch_bounds__(256) void proj_mma(
    const float* __restrict__ b1, const float* __restrict__ b2)
{
    __shared__ __nv_bfloat16 sXh[2][BM * XSTR], sXl[2][BM * XSTR];
    __shared__ __nv_bfloat16 sWh[2][BN * XSTR], sWl[2][BN * XSTR];

    const int m0 = blockIdx.x * BM;
    const int n0 = blockIdx.y * BN;
    const bool isQ = (m0 < MQ);
    const int woff = isQ ? 0 : 512 * DD;
    const __nv_bfloat16* Xhg = g_xhi_bf + (size_t)m0 * DD;
    const __nv_bfloat16* Xlg = g_xlo_bf + (size_t)m0 * DD;
    const __nv_bfloat16* Whg = g_whi_bf + woff + (size_t)n0 * DD;
    const __nv_bfloat16* Wlg = g_wlo_bf + woff + (size_t)n0 * DD;
    const float* bias = isQ ? b2 : b1;
    float* out = isQ ? (g_qt + (size_t)m0 * DD) : (g_kt + (size_t)(m0 - MQ) * DD);

    const int tid = threadIdx.x;
    const int wid = tid >> 5, lane = tid & 31;
    const int wm = (wid & 3) * 32;     // warp m offset
    const int wn = (wid >> 2) * 32;    // warp n offset
    const int gr = lane >> 2;          // 0..7
    const int gc = lane & 3;           // 0..3

    float acc[2][4][4];
#pragma unroll
    for (int mf = 0; mf < 2; mf++)
#pragma unroll
        for (int nf = 0; nf < 4; nf++)
#pragma unroll
            for (int j = 0; j < 4; j++) acc[mf][nf][j] = 0.0f;

    auto load_stage = [&](int st, int kc) {
        const int kb = kc * PKC;
        {
            int r = tid >> 1, k8 = (tid & 1) * 8;
            cp16(&sXh[st][r * XSTR + k8], Xhg + r * DD + kb + k8);
            cp16(&sXl[st][r * XSTR + k8], Xlg + r * DD + kb + k8);
        }
        if (tid < 128) {
            int r = tid >> 1, k8 = (tid & 1) * 8;
            cp16(&sWh[st][r * XSTR + k8], Whg + r * DD + kb + k8);
        } else {
            int t2 = tid - 128;
            int r = t2 >> 1, k8 = (t2 & 1) * 8;
            cp16(&sWl[st][r * XSTR + k8], Wlg + r * DD + kb + k8);
        }
        CP_COMMIT;
    };

    load_stage(0, 0);

    const int NCH = DD / PKC;   // 32
    for (int kc = 0; kc < NCH; kc++) {
        const int st = kc & 1;
        if (kc + 1 < NCH) {
            load_stage(st ^ 1, kc + 1);
            CP_WAIT1;
        } else {
            CP_WAIT0;
        }
        __syncthreads();

        uint32_t ah[2][4], al[2][4];
#pragma unroll
        for (int mf = 0; mf < 2; mf++) {
            int rb = (wm + mf * 16 + gr) * XSTR + gc * 2;
            ah[mf][0] = *(const uint32_t*)&sXh[st][rb];
            ah[mf][1] = *(const uint32_t*)&sXh[st][rb + 8 * XSTR];
            ah[mf][2] = *(const uint32_t*)&sXh[st][rb + 8];
            ah[mf][3] = *(const uint32_t*)&sXh[st][rb + 8 * XSTR + 8];
            al[mf][0] = *(const uint32_t*)&sXl[st][rb];
            al[mf][1] = *(const uint32_t*)&sXl[st][rb + 8 * XSTR];
            al[mf][2] = *(const uint32_t*)&sXl[st][rb + 8];
            al[mf][3] = *(const uint32_t*)&sXl[st][rb + 8 * XSTR + 8];
        }
#pragma unroll
        for (int nf = 0; nf < 4; nf++) {
            int nb = (wn + nf * 8 + gr) * XSTR + gc * 2;
            uint32_t bh0 = *(const uint32_t*)&sWh[st][nb];
            uint32_t bh1 = *(const uint32_t*)&sWh[st][nb + 8];
            uint32_t bl0 = *(const uint32_t*)&sWl[st][nb];
            uint32_t bl1 = *(const uint32_t*)&sWl[st][nb + 8];
#pragma unroll
            for (int mf = 0; mf < 2; mf++) {
                MMA_BF16(acc[mf][nf], ah[mf], bh0, bh1);
                MMA_BF16(acc[mf][nf], al[mf], bh0, bh1);
                MMA_BF16(acc[mf][nf], ah[mf], bl0, bl1);
            }
        }
        __syncthreads();
    }

    // Epilogue: + bias, f32 store
#pragma unroll
    for (int nf = 0; nf < 4; nf++) {
        int col = wn + nf * 8 + 2 * gc;
        float2 bb = *(const float2*)&bias[n0 + col];
#pragma unroll
        for (int mf = 0; mf < 2; mf++) {
            int row = wm + mf * 16 + gr;
            float2 o0, o1;
            o0.x = acc[mf][nf][0] + bb.x;  o0.y = acc[mf][nf][1] + bb.y;
            o1.x = acc[mf][nf][2] + bb.x;  o1.y = acc[mf][nf][3] + bb.y;
            *(float2*)&out[row * DD + n0 + col] = o0;
            *(float2*)&out[(row + 8) * DD + n0 + col] = o1;
        }
    }
}

// ---------------------------------------------------------------------------
// Score: scores[b,q,k] = sum_d v[d] * tanh(qt[b,q,d] + kt[b,k,d])
// Tile 16q x 32k, 128 threads, 2x2 micro-tile, 512 blocks (fine-grained SM
// balance). MUFU(tanh)-bound: per d-step 4 MUFU vs 8 fma-pipe ops per thread.
// ---------------------------------------------------------------------------
#define SQ 16
#define SK 32
#define SD 64

__global__ __launch_bounds__(128) void score_kernel(
    const float* __restrict__ v, float* __restrict__ out)
{
    __shared__ float qs[SQ][SD + 1];
    __shared__ float ks[SK][SD + 1];
    __shared__ float vs[SD];

    const int b  = blockIdx.z;
    const int q0 = blockIdx.y * SQ;
    const int k0 = blockIdx.x * SK;
    const float* qt = g_qt + ((size_t)b * NQ + q0) * DD;
    const float* kt = g_kt + ((size_t)b * NK + k0) * DD;

    const int tid = threadIdx.x;
    const int tk = tid & 15;    // 2 k each
    const int tq = tid >> 4;    // 2 q each

    float acc[2][2] = {{0.f, 0.f}, {0.f, 0.f}};

    for (int dc = 0; dc < DD; dc += SD) {
        // qs: 16x64 = 256 float4, 2 per thread
#pragma unroll
        for (int i = 0; i < 2; i++) {
            int idx = tid + i * 128;
            int r = idx >> 4, c4 = (idx & 15) * 4;
            float4 t = *(const float4*)&qt[r * DD + dc + c4];
            qs[r][c4] = t.x; qs[r][c4 + 1] = t.y;
            qs[r][c4 + 2] = t.z; qs[r][c4 + 3] = t.w;
        }
        // ks: 32x64 = 512 float4, 4 per thread
#pragma unroll
        for (int i = 0; i < 4; i++) {
            int idx = tid + i * 128;
            int r = idx >> 4, c4 = (idx & 15) * 4;
            float4 t = *(const float4*)&kt[r * DD + dc + c4];
            ks[r][c4] = t.x; ks[r][c4 + 1] = t.y;
            ks[r][c4 + 2] = t.z; ks[r][c4 + 3] = t.w;
        }
        if (tid < SD) vs[tid] = v[dc + tid];
        __syncthreads();

#pragma unroll 8
        for (int dd = 0; dd < SD; dd++) {
            float vq0 = qs[tq * 2 + 0][dd];
            float vq1 = qs[tq * 2 + 1][dd];
            float kv0 = ks[tk * 2 + 0][dd];
            float kv1 = ks[tk * 2 + 1][dd];
            float vd  = vs[dd];
            acc[0][0] = fmaf(vd, fast_tanh(vq0 + kv0), acc[0][0]);
            acc[0][1] = fmaf(vd, fast_tanh(vq0 + kv1), acc[0][1]);
            acc[1][0] = fmaf(vd, fast_tanh(vq1 + kv0), acc[1][0]);
            acc[1][1] = fmaf(vd, fast_tanh(vq1 + kv1), acc[1][1]);
        }
        __syncthreads();
    }

#pragma unroll
    for (int i = 0; i < 2; i++) {
        float2 o;
        o.x = acc[i][0]; o.y = acc[i][1];
        *(float2*)&out[((size_t)b * NQ + q0 + tq * 2 + i) * NK + k0 + tk * 2] = o;
    }
}

extern "C" void kernel_launch(void* const* d_in, const int* in_sizes, int n_in,
                              void* d_out, int out_size)
{
    const float* query = (const float*)d_in[0];  // [8,128,512]
    const float* key   = (const float*)d_in[1];  // [8,256,512]
    const float* W1    = (const float*)d_in[2];  // [512,512]
    const float* b1    = (const float*)d_in[3];  // [512]
    const float* W2    = (const float*)d_in[4];  // [512,512]
    const float* b2    = (const float*)d_in[5];  // [512]
    const float* v     = (const float*)d_in[6];  // [512]
    float* out = (float*)d_out;                  // [8,128,256]

    convert_kernel<<<1024, 256>>>((const float4*)query, (const float4*)key,
                                  (const float4*)W1, (const float4*)W2);
    // 24 m-tiles (3072/128) x 8 n-tiles (512/64)
    proj_mma<<<dim3(24, 8), 256>>>(b1, b2);
    // 8 k-tiles x 8 q-tiles x 8 batches = 512 blocks
    score_kernel<<<dim3(NK / SK, NQ / SQ, NB), 128>>>(v, out);
}

// round 5
// speedup vs baseline: 1.2854x; 1.0502x over previous
#include <cuda_runtime.h>
#include <cuda_bf16.h>
#include <cstdint>

#define DD 512
#define NB 8
#define NQ 128
#define NK 256
#define MQ (NB * NQ)            // 1024 query rows
#define MTOT (MQ + NB * NK)     // 3072 total rows

// ---------------------------------------------------------------------------
// Device scratch (graph-capture safe)
// ---------------------------------------------------------------------------
__device__ float g_qt[MQ * DD];               // projected queries (2 MB)
__device__ float g_kt[NB * NK * DD];          // projected keys    (4 MB)
__device__ __nv_bfloat16 g_xhi_bf[MTOT * DD]; // bf16-hi of [query;key]
__device__ __nv_bfloat16 g_xlo_bf[MTOT * DD]; // bf16-lo residual
__device__ __nv_bfloat16 g_whi_bf[1024 * DD]; // rows 0-511: W2, 512-1023: W1
__device__ __nv_bfloat16 g_wlo_bf[1024 * DD];

__device__ __forceinline__ float fast_tanh(float x) {
    float y;
    asm("tanh.approx.f32 %0, %1;" : "=f"(y) : "f"(x));
    return y;
}

__device__ __forceinline__ void bf16_split(float x, __nv_bfloat16& h, __nv_bfloat16& l) {
    h = __float2bfloat16_rn(x);
    l = __float2bfloat16_rn(x - __bfloat162float(h));
}

__device__ __forceinline__ void cp16(void* smem, const void* gmem) {
    unsigned s = (unsigned)__cvta_generic_to_shared(smem);
    asm volatile("cp.async.cg.shared.global [%0], [%1], 16;" :: "r"(s), "l"(gmem));
}
#define CP_COMMIT asm volatile("cp.async.commit_group;")
#define CP_WAIT1  asm volatile("cp.async.wait_group 1;")
#define CP_WAIT0  asm volatile("cp.async.wait_group 0;")

// ---------------------------------------------------------------------------
// Convert: split GEMM operands into bf16 hi/lo planes (near BW floor).
//   blocks [0,256) -> query  [256,768) -> key  [768,896) -> W2  [896,1024) -> W1
// ---------------------------------------------------------------------------
__global__ __launch_bounds__(256) void convert_kernel(
    const float4* __restrict__ query, const float4* __restrict__ key,
    const float4* __restrict__ W1, const float4* __restrict__ W2)
{
    const int bi = blockIdx.x;
    const float4* src;
    __nv_bfloat16 *dh, *dl;
    int base;
    if (bi < 256) {
        src = query; dh = g_xhi_bf; dl = g_xlo_bf; base = bi * 512;
    } else if (bi < 768) {
        src = key; dh = g_xhi_bf + MQ * DD; dl = g_xlo_bf + MQ * DD;
        base = (bi - 256) * 512;
    } else if (bi < 896) {
        src = W2; dh = g_whi_bf; dl = g_wlo_bf; base = (bi - 768) * 512;
    } else {
        src = W1; dh = g_whi_bf + 512 * DD; dl = g_wlo_bf + 512 * DD;
        base = (bi - 896) * 512;
    }
#pragma unroll
    for (int i = 0; i < 2; i++) {
        int idx = base + threadIdx.x + i * 256;
        float4 t = src[idx];
        __nv_bfloat16 h[4], l[4];
        bf16_split(t.x, h[0], l[0]);
        bf16_split(t.y, h[1], l[1]);
        bf16_split(t.z, h[2], l[2]);
        bf16_split(t.w, h[3], l[3]);
        *(uint2*)&dh[(size_t)idx * 4] = *(uint2*)h;
        *(uint2*)&dl[(size_t)idx * 4] = *(uint2*)l;
    }
}

// ---------------------------------------------------------------------------
// Projection GEMM, bf16 m16n8k16 with 3-term compensation:
//   C = Xhi*Whi^T + Xlo*Whi^T + Xhi*Wlo^T (+ bias)
// Tile 64m x 64n, 128 threads (4 warps, 2x2 of 32x32), k-chunk 16,
// cp.async double-buffered. 384 blocks -> ~2.6/SM, no wave cliff.
// Smem rows stride 24 bf16 (48B, 16B-aligned) -> fragment LDS conflict-free.
// ---------------------------------------------------------------------------
#define BM 64
#define BN 64
#define PKC 16
#define XSTR 24

#define MMA_BF16(c, a, b0_, b1_)                                               \
    asm volatile(                                                              \
        "mma.sync.aligned.m16n8k16.row.col.f32.bf16.bf16.f32 "                 \
        "{%0,%1,%2,%3}, {%4,%5,%6,%7}, {%8,%9}, {%0,%1,%2,%3};"                \
        : "+f"((c)[0]), "+f"((c)[1]), "+f"((c)[2]), "+f"((c)[3])               \
        : "r"((a)[0]), "r"((a)[1]), "r"((a)[2]), "r"((a)[3]),                  \
          "r"(b0_), "r"(b1_))

__global__ __launch_bounds__(128) void proj_mma(
    const float* __restrict__ b1, const float* __restrict__ b2)
{
    __shared__ __nv_bfloat16 sXh[2][BM * XSTR], sXl[2][BM * XSTR];
    __shared__ __nv_bfloat16 sWh[2][BN * XSTR], sWl[2][BN * XSTR];

    const int m0 = blockIdx.x * BM;
    const int n0 = blockIdx.y * BN;
    const bool isQ = (m0 < MQ);
    const int woff = isQ ? 0 : 512 * DD;
    const __nv_bfloat16* Xhg = g_xhi_bf + (size_t)m0 * DD;
    const __nv_bfloat16* Xlg = g_xlo_bf + (size_t)m0 * DD;
    const __nv_bfloat16* Whg = g_whi_bf + woff + (size_t)n0 * DD;
    const __nv_bfloat16* Wlg = g_wlo_bf + woff + (size_t)n0 * DD;
    const float* bias = isQ ? b2 : b1;
    float* out = isQ ? (g_qt + (size_t)m0 * DD) : (g_kt + (size_t)(m0 - MQ) * DD);

    const int tid = threadIdx.x;
    const int wid = tid >> 5, lane = tid & 31;
    const int wm = (wid & 1) * 32;     // warp m offset
    const int wn = (wid >> 1) * 32;    // warp n offset
    const int gr = lane >> 2;          // 0..7
    const int gc = lane & 3;           // 0..3

    float acc[2][4][4];
#pragma unroll
    for (int mf = 0; mf < 2; mf++)
#pragma unroll
        for (int nf = 0; nf < 4; nf++)
#pragma unroll
            for (int j = 0; j < 4; j++) acc[mf][nf][j] = 0.0f;

    auto load_stage = [&](int st, int kc) {
        const int kb = kc * PKC;
        int r = tid >> 1, k8 = (tid & 1) * 8;     // r in 0..63
        cp16(&sXh[st][r * XSTR + k8], Xhg + r * DD + kb + k8);
        cp16(&sXl[st][r * XSTR + k8], Xlg + r * DD + kb + k8);
        cp16(&sWh[st][r * XSTR + k8], Whg + r * DD + kb + k8);
        cp16(&sWl[st][r * XSTR + k8], Wlg + r * DD + kb + k8);
        CP_COMMIT;
    };

    load_stage(0, 0);

    const int NCH = DD / PKC;   // 32
    for (int kc = 0; kc < NCH; kc++) {
        const int st = kc & 1;
        if (kc + 1 < NCH) {
            load_stage(st ^ 1, kc + 1);
            CP_WAIT1;
        } else {
            CP_WAIT0;
        }
        __syncthreads();

        uint32_t ah[2][4], al[2][4];
#pragma unroll
        for (int mf = 0; mf < 2; mf++) {
            int rb = (wm + mf * 16 + gr) * XSTR + gc * 2;
            ah[mf][0] = *(const uint32_t*)&sXh[st][rb];
            ah[mf][1] = *(const uint32_t*)&sXh[st][rb + 8 * XSTR];
            ah[mf][2] = *(const uint32_t*)&sXh[st][rb + 8];
            ah[mf][3] = *(const uint32_t*)&sXh[st][rb + 8 * XSTR + 8];
            al[mf][0] = *(const uint32_t*)&sXl[st][rb];
            al[mf][1] = *(const uint32_t*)&sXl[st][rb + 8 * XSTR];
            al[mf][2] = *(const uint32_t*)&sXl[st][rb + 8];
            al[mf][3] = *(const uint32_t*)&sXl[st][rb + 8 * XSTR + 8];
        }
#pragma unroll
        for (int nf = 0; nf < 4; nf++) {
            int nb = (wn + nf * 8 + gr) * XSTR + gc * 2;
            uint32_t bh0 = *(const uint32_t*)&sWh[st][nb];
            uint32_t bh1 = *(const uint32_t*)&sWh[st][nb + 8];
            uint32_t bl0 = *(const uint32_t*)&sWl[st][nb];
            uint32_t bl1 = *(const uint32_t*)&sWl[st][nb + 8];
#pragma unroll
            for (int mf = 0; mf < 2; mf++) {
                MMA_BF16(acc[mf][nf], ah[mf], bh0, bh1);
                MMA_BF16(acc[mf][nf], al[mf], bh0, bh1);
                MMA_BF16(acc[mf][nf], ah[mf], bl0, bl1);
            }
        }
        __syncthreads();
    }

    // Epilogue: + bias, f32 store
#pragma unroll
    for (int nf = 0; nf < 4; nf++) {
        int col = wn + nf * 8 + 2 * gc;
        float2 bb = *(const float2*)&bias[n0 + col];
#pragma unroll
        for (int mf = 0; mf < 2; mf++) {
            int row = wm + mf * 16 + gr;
            float2 o0, o1;
            o0.x = acc[mf][nf][0] + bb.x;  o0.y = acc[mf][nf][1] + bb.y;
            o1.x = acc[mf][nf][2] + bb.x;  o1.y = acc[mf][nf][3] + bb.y;
            *(float2*)&out[row * DD + n0 + col] = o0;
            *(float2*)&out[(row + 8) * DD + n0 + col] = o1;
        }
    }
}

// ---------------------------------------------------------------------------
// Score: scores[b,q,k] = sum_d v[d] * tanh(qt[b,q,d] + kt[b,k,d])
// Tile 16q x 32k, 128 threads, 2x2 micro-tile, 512 blocks.
// Register-staged double buffering: next D-chunk LDGs issue at the top of the
// compute phase, so the MUFU pipe never idles on loads. MUFU(tanh)-bound.
// ---------------------------------------------------------------------------
#define SQ 16
#define SK 32
#define SD 64

__global__ __launch_bounds__(128) void score_kernel(
    const float* __restrict__ v, float* __restrict__ out)
{
    __shared__ float qs[SQ][SD + 1];
    __shared__ float ks[SK][SD + 1];
    __shared__ float vs[DD];

    const int b  = blockIdx.z;
    const int q0 = blockIdx.y * SQ;
    const int k0 = blockIdx.x * SK;
    const float* qt = g_qt + ((size_t)b * NQ + q0) * DD;
    const float* kt = g_kt + ((size_t)b * NK + k0) * DD;

    const int tid = threadIdx.x;
    const int tk = tid & 15;    // 2 k each
    const int tq = tid >> 4;    // 2 q each

    // v -> smem once (512 floats, 4 per thread)
    *(float4*)&vs[tid * 4] = *(const float4*)&v[tid * 4];

    // Per-thread staging registers for one D-chunk
    float4 rq[2], rk[4];
    auto prefetch = [&](int dc) {
#pragma unroll
        for (int i = 0; i < 2; i++) {
            int idx = tid + i * 128;
            int r = idx >> 4, c4 = (idx & 15) * 4;
            rq[i] = *(const float4*)&qt[r * DD + dc + c4];
        }
#pragma unroll
        for (int i = 0; i < 4; i++) {
            int idx = tid + i * 128;
            int r = idx >> 4, c4 = (idx & 15) * 4;
            rk[i] = *(const float4*)&kt[r * DD + dc + c4];
        }
    };

    prefetch(0);

    float acc[2][2] = {{0.f, 0.f}, {0.f, 0.f}};

    for (int dc = 0; dc < DD; dc += SD) {
        // Commit staged registers to smem
#pragma unroll
        for (int i = 0; i < 2; i++) {
            int idx = tid + i * 128;
            int r = idx >> 4, c4 = (idx & 15) * 4;
            qs[r][c4] = rq[i].x; qs[r][c4 + 1] = rq[i].y;
            qs[r][c4 + 2] = rq[i].z; qs[r][c4 + 3] = rq[i].w;
        }
#pragma unroll
        for (int i = 0; i < 4; i++) {
            int idx = tid + i * 128;
            int r = idx >> 4, c4 = (idx & 15) * 4;
            ks[r][c4] = rk[i].x; ks[r][c4 + 1] = rk[i].y;
            ks[r][c4 + 2] = rk[i].z; ks[r][c4 + 3] = rk[i].w;
        }
        __syncthreads();

        // Issue next chunk's global loads NOW; they drain during compute.
        if (dc + SD < DD) prefetch(dc + SD);

        const float* vp = &vs[dc];
#pragma unroll 16
        for (int dd = 0; dd < SD; dd++) {
            float vq0 = qs[tq * 2 + 0][dd];
            float vq1 = qs[tq * 2 + 1][dd];
            float kv0 = ks[tk * 2 + 0][dd];
            float kv1 = ks[tk * 2 + 1][dd];
            float vd  = vp[dd];
            acc[0][0] = fmaf(vd, fast_tanh(vq0 + kv0), acc[0][0]);
            acc[0][1] = fmaf(vd, fast_tanh(vq0 + kv1), acc[0][1]);
            acc[1][0] = fmaf(vd, fast_tanh(vq1 + kv0), acc[1][0]);
            acc[1][1] = fmaf(vd, fast_tanh(vq1 + kv1), acc[1][1]);
        }
        __syncthreads();
    }

#pragma unroll
    for (int i = 0; i < 2; i++) {
        float2 o;
        o.x = acc[i][0]; o.y = acc[i][1];
        *(float2*)&out[((size_t)b * NQ + q0 + tq * 2 + i) * NK + k0 + tk * 2] = o;
    }
}

extern "C" void kernel_launch(void* const* d_in, const int* in_sizes, int n_in,
                              void* d_out, int out_size)
{
    const float* query = (const float*)d_in[0];  // [8,128,512]
    const float* key   = (const float*)d_in[1];  // [8,256,512]
    const float* W1    = (const float*)d_in[2];  // [512,512]
    const float* b1    = (const float*)d_in[3];  // [512]
    const float* W2    = (const float*)d_in[4];  // [512,512]
    const float* b2    = (const float*)d_in[5];  // [512]
    const float* v     = (const float*)d_in[6];  // [512]
    float* out = (float*)d_out;                  // [8,128,256]

    convert_kernel<<<1024, 256>>>((const float4*)query, (const float4*)key,
                                  (const float4*)W1, (const float4*)W2);
    // 48 m-tiles (3072/64) x 8 n-tiles (512/64) = 384 blocks
    proj_mma<<<dim3(48, 8), 128>>>(b1, b2);
    // 8 k-tiles x 8 q-tiles x 8 batches = 512 blocks
    score_kernel<<<dim3(NK / SK, NQ / SQ, NB), 128>>>(v, out);
}

// round 6
// speedup vs baseline: 1.4321x; 1.1141x over previous
#include <cuda_runtime.h>
#include <cuda_bf16.h>
#include <cstdint>

#define DD 512
#define NB 8
#define NQ 128
#define NK 256
#define MQ (NB * NQ)            // 1024 query rows
#define MTOT (MQ + NB * NK)     // 3072 total rows

// ---------------------------------------------------------------------------
// Device scratch (graph-capture safe)
// ---------------------------------------------------------------------------
__device__ float g_qt[MQ * DD];               // projected queries (2 MB)
__device__ float g_kt[NB * NK * DD];          // projected keys    (4 MB)
__device__ __nv_bfloat16 g_xhi_bf[MTOT * DD]; // bf16-hi of [query;key]
__device__ __nv_bfloat16 g_xlo_bf[MTOT * DD]; // bf16-lo residual
__device__ __nv_bfloat16 g_whi_bf[1024 * DD]; // rows 0-511: W2, 512-1023: W1
__device__ __nv_bfloat16 g_wlo_bf[1024 * DD];

__device__ __forceinline__ float fast_tanh(float x) {
    float y;
    asm("tanh.approx.f32 %0, %1;" : "=f"(y) : "f"(x));
    return y;
}

__device__ __forceinline__ void bf16_split(float x, __nv_bfloat16& h, __nv_bfloat16& l) {
    h = __float2bfloat16_rn(x);
    l = __float2bfloat16_rn(x - __bfloat162float(h));
}

__device__ __forceinline__ void cp16(void* smem, const void* gmem) {
    unsigned s = (unsigned)__cvta_generic_to_shared(smem);
    asm volatile("cp.async.cg.shared.global [%0], [%1], 16;" :: "r"(s), "l"(gmem));
}
#define CP_COMMIT asm volatile("cp.async.commit_group;")
#define CP_WAIT1  asm volatile("cp.async.wait_group 1;")
#define CP_WAIT0  asm volatile("cp.async.wait_group 0;")

#define LDSM4(d0, d1, d2, d3, a)                                               \
    asm volatile("ldmatrix.sync.aligned.m8n8.x4.shared.b16 {%0,%1,%2,%3}, [%4];" \
                 : "=r"(d0), "=r"(d1), "=r"(d2), "=r"(d3) : "r"(a))
#define LDSM2(d0, d1, a)                                                       \
    asm volatile("ldmatrix.sync.aligned.m8n8.x2.shared.b16 {%0,%1}, [%2];"     \
                 : "=r"(d0), "=r"(d1) : "r"(a))

// ---------------------------------------------------------------------------
// Convert: split GEMM operands into bf16 hi/lo planes (near BW floor).
// ---------------------------------------------------------------------------
__global__ __launch_bounds__(256) void convert_kernel(
    const float4* __restrict__ query, const float4* __restrict__ key,
    const float4* __restrict__ W1, const float4* __restrict__ W2)
{
    const int bi = blockIdx.x;
    const float4* src;
    __nv_bfloat16 *dh, *dl;
    int base;
    if (bi < 256) {
        src = query; dh = g_xhi_bf; dl = g_xlo_bf; base = bi * 512;
    } else if (bi < 768) {
        src = key; dh = g_xhi_bf + MQ * DD; dl = g_xlo_bf + MQ * DD;
        base = (bi - 256) * 512;
    } else if (bi < 896) {
        src = W2; dh = g_whi_bf; dl = g_wlo_bf; base = (bi - 768) * 512;
    } else {
        src = W1; dh = g_whi_bf + 512 * DD; dl = g_wlo_bf + 512 * DD;
        base = (bi - 896) * 512;
    }
#pragma unroll
    for (int i = 0; i < 2; i++) {
        int idx = base + threadIdx.x + i * 256;
        float4 t = src[idx];
        __nv_bfloat16 h[4], l[4];
        bf16_split(t.x, h[0], l[0]);
        bf16_split(t.y, h[1], l[1]);
        bf16_split(t.z, h[2], l[2]);
        bf16_split(t.w, h[3], l[3]);
        *(uint2*)&dh[(size_t)idx * 4] = *(uint2*)h;
        *(uint2*)&dl[(size_t)idx * 4] = *(uint2*)l;
    }
}

// ---------------------------------------------------------------------------
// Projection GEMM, bf16 m16n8k16, 3-term compensation, ldmatrix fragments.
// Tile 64m x 64n, 128 threads (2x2 warps of 32x32), k-chunk 32 (16 phases),
// cp.async double-buffered. Smem rows stride 40 bf16 -> ldmatrix conflict-free.
// ---------------------------------------------------------------------------
#define BM 64
#define BN 64
#define PKC 32
#define XSTR 40

#define MMA_BF16(c, a, b0_, b1_)                                               \
    asm volatile(                                                              \
        "mma.sync.aligned.m16n8k16.row.col.f32.bf16.bf16.f32 "                 \
        "{%0,%1,%2,%3}, {%4,%5,%6,%7}, {%8,%9}, {%0,%1,%2,%3};"                \
        : "+f"((c)[0]), "+f"((c)[1]), "+f"((c)[2]), "+f"((c)[3])               \
        : "r"((a)[0]), "r"((a)[1]), "r"((a)[2]), "r"((a)[3]),                  \
          "r"(b0_), "r"(b1_))

__global__ __launch_bounds__(128) void proj_mma(
    const float* __restrict__ b1, const float* __restrict__ b2)
{
    __shared__ __nv_bfloat16 sXh[2][BM * XSTR], sXl[2][BM * XSTR];
    __shared__ __nv_bfloat16 sWh[2][BN * XSTR], sWl[2][BN * XSTR];

    const int m0 = blockIdx.x * BM;
    const int n0 = blockIdx.y * BN;
    const bool isQ = (m0 < MQ);
    const int woff = isQ ? 0 : 512 * DD;
    const __nv_bfloat16* Xhg = g_xhi_bf + (size_t)m0 * DD;
    const __nv_bfloat16* Xlg = g_xlo_bf + (size_t)m0 * DD;
    const __nv_bfloat16* Whg = g_whi_bf + woff + (size_t)n0 * DD;
    const __nv_bfloat16* Wlg = g_wlo_bf + woff + (size_t)n0 * DD;
    const float* bias = isQ ? b2 : b1;
    float* out = isQ ? (g_qt + (size_t)m0 * DD) : (g_kt + (size_t)(m0 - MQ) * DD);

    const int tid = threadIdx.x;
    const int wid = tid >> 5, lane = tid & 31;
    const int wm = (wid & 1) * 32;     // warp m offset
    const int wn = (wid >> 1) * 32;    // warp n offset
    const int gr = lane >> 2;          // 0..7  (fragment row group)
    const int gc = lane & 3;           // 0..3

    // ldmatrix lane->address row/col components
    const int grp = lane >> 3, lr = lane & 7;
    const int a_r = (grp & 1) * 8 + lr;        // A: row within 16-row frag
    const int a_c = (grp >> 1) * 8;            // A: col 0/8 within k16
    const int b_r = lr;                        // B: n-row within 8
    const int b_c = (grp & 1) * 8;             // B: col 0/8 (lanes>=16 unused)

    float acc[2][4][4];
#pragma unroll
    for (int mf = 0; mf < 2; mf++)
#pragma unroll
        for (int nf = 0; nf < 4; nf++)
#pragma unroll
            for (int j = 0; j < 4; j++) acc[mf][nf][j] = 0.0f;

    auto load_stage = [&](int st, int kc) {
        const int kb = kc * PKC;
#pragma unroll
        for (int i = 0; i < 2; i++) {
            int idx = tid + i * 128;           // 0..255
            int r = idx >> 2, c8 = (idx & 3) * 8;
            int so = r * XSTR + c8;
            size_t go = (size_t)r * DD + kb + c8;
            cp16(&sXh[st][so], Xhg + go);
            cp16(&sXl[st][so], Xlg + go);
            cp16(&sWh[st][so], Whg + go);
            cp16(&sWl[st][so], Wlg + go);
        }
        CP_COMMIT;
    };

    load_stage(0, 0);

    const int NCH = DD / PKC;   // 16
    for (int kc = 0; kc < NCH; kc++) {
        const int st = kc & 1;
        if (kc + 1 < NCH) {
            load_stage(st ^ 1, kc + 1);
            CP_WAIT1;
        } else {
            CP_WAIT0;
        }
        __syncthreads();

#pragma unroll
        for (int k16 = 0; k16 < PKC; k16 += 16) {
            uint32_t ah[2][4], al[2][4];
#pragma unroll
            for (int mf = 0; mf < 2; mf++) {
                unsigned aoff = (unsigned)((wm + mf * 16 + a_r) * XSTR + k16 + a_c);
                unsigned pah = (unsigned)__cvta_generic_to_shared(&sXh[st][aoff]);
                unsigned pal = (unsigned)__cvta_generic_to_shared(&sXl[st][aoff]);
                LDSM4(ah[mf][0], ah[mf][1], ah[mf][2], ah[mf][3], pah);
                LDSM4(al[mf][0], al[mf][1], al[mf][2], al[mf][3], pal);
            }
#pragma unroll
            for (int nf = 0; nf < 4; nf++) {
                unsigned boff = (unsigned)((wn + nf * 8 + b_r) * XSTR + k16 + b_c);
                unsigned pbh = (unsigned)__cvta_generic_to_shared(&sWh[st][boff]);
                unsigned pbl = (unsigned)__cvta_generic_to_shared(&sWl[st][boff]);
                uint32_t bh0, bh1, bl0, bl1;
                LDSM2(bh0, bh1, pbh);
                LDSM2(bl0, bl1, pbl);
#pragma unroll
                for (int mf = 0; mf < 2; mf++) {
                    MMA_BF16(acc[mf][nf], ah[mf], bh0, bh1);
                    MMA_BF16(acc[mf][nf], al[mf], bh0, bh1);
                    MMA_BF16(acc[mf][nf], ah[mf], bl0, bl1);
                }
            }
        }
        __syncthreads();
    }

    // Epilogue: + bias, f32 store
#pragma unroll
    for (int nf = 0; nf < 4; nf++) {
        int col = wn + nf * 8 + 2 * gc;
        float2 bb = *(const float2*)&bias[n0 + col];
#pragma unroll
        for (int mf = 0; mf < 2; mf++) {
            int row = wm + mf * 16 + gr;
            float2 o0, o1;
            o0.x = acc[mf][nf][0] + bb.x;  o0.y = acc[mf][nf][1] + bb.y;
            o1.x = acc[mf][nf][2] + bb.x;  o1.y = acc[mf][nf][3] + bb.y;
            *(float2*)&out[row * DD + n0 + col] = o0;
            *(float2*)&out[(row + 8) * DD + n0 + col] = o1;
        }
    }
}

// ---------------------------------------------------------------------------
// Score: scores[b,q,k] = sum_d v[d] * tanh(qt[b,q,d] + kt[b,k,d])
// Tile 16q x 32k, 128 threads, 2x2 micro-tile, 512 blocks.
// k tile stored dd-major in smem -> inner loop processes 4 d per step with
// 2 LDS.128 (q, broadcast) + 4 LDS.64 (k) + 1 LDS.128 (v) per 16 tanh.
// Register-staged prefetch hides global latency. MUFU(tanh)-bound.
// ---------------------------------------------------------------------------
#define SQ 16
#define SK 32
#define SD 64

__global__ __launch_bounds__(128) void score_kernel(
    const float* __restrict__ v, float* __restrict__ out)
{
    __shared__ float qs[SQ][68];      // q-major, 272B rows (16B aligned)
    __shared__ float ks[SD][34];      // dd-major (transposed), 136B rows
    __shared__ float vs[DD];

    const int b  = blockIdx.z;
    const int q0 = blockIdx.y * SQ;
    const int k0 = blockIdx.x * SK;
    const float* qt = g_qt + ((size_t)b * NQ + q0) * DD;
    const float* kt = g_kt + ((size_t)b * NK + k0) * DD;

    const int tid = threadIdx.x;
    const int tk = tid & 15;    // 2 k each
    const int tq = tid >> 4;    // 2 q each

    // v -> smem once (512 floats, 4 per thread)
    *(float4*)&vs[tid * 4] = *(const float4*)&v[tid * 4];

    // Per-thread staging registers for one D-chunk
    float4 rq[2], rk[4];
    auto prefetch = [&](int dc) {
#pragma unroll
        for (int i = 0; i < 2; i++) {
            int idx = tid + i * 128;
            int r = idx >> 4, c4 = (idx & 15) * 4;
            rq[i] = *(const float4*)&qt[r * DD + dc + c4];
        }
#pragma unroll
        for (int i = 0; i < 4; i++) {
            int idx = tid + i * 128;
            int r = idx >> 4, c4 = (idx & 15) * 4;
            rk[i] = *(const float4*)&kt[r * DD + dc + c4];
        }
    };

    prefetch(0);

    float a00 = 0.f, a01 = 0.f, a10 = 0.f, a11 = 0.f;

    for (int dc = 0; dc < DD; dc += SD) {
        // Commit staged registers to smem (k transposed to dd-major)
#pragma unroll
        for (int i = 0; i < 2; i++) {
            int idx = tid + i * 128;
            int r = idx >> 4, c4 = (idx & 15) * 4;
            *(float4*)&qs[r][c4] = rq[i];
        }
#pragma unroll
        for (int i = 0; i < 4; i++) {
            int idx = tid + i * 128;
            int r = idx >> 4, c4 = (idx & 15) * 4;
            ks[c4 + 0][r] = rk[i].x;
            ks[c4 + 1][r] = rk[i].y;
            ks[c4 + 2][r] = rk[i].z;
            ks[c4 + 3][r] = rk[i].w;
        }
        __syncthreads();

        // Issue next chunk's global loads NOW; they drain during compute.
        if (dc + SD < DD) prefetch(dc + SD);

#pragma unroll
        for (int d4 = 0; d4 < SD; d4 += 4) {
            float4 q0v = *(const float4*)&qs[tq * 2 + 0][d4];
            float4 q1v = *(const float4*)&qs[tq * 2 + 1][d4];
            float2 kk0 = *(const float2*)&ks[d4 + 0][tk * 2];
            float2 kk1 = *(const float2*)&ks[d4 + 1][tk * 2];
            float2 kk2 = *(const float2*)&ks[d4 + 2][tk * 2];
            float2 kk3 = *(const float2*)&ks[d4 + 3][tk * 2];
            float4 vv  = *(const float4*)&vs[dc + d4];

            a00 = fmaf(vv.x, fast_tanh(q0v.x + kk0.x), a00);
            a01 = fmaf(vv.x, fast_tanh(q0v.x + kk0.y), a01);
            a10 = fmaf(vv.x, fast_tanh(q1v.x + kk0.x), a10);
            a11 = fmaf(vv.x, fast_tanh(q1v.x + kk0.y), a11);

            a00 = fmaf(vv.y, fast_tanh(q0v.y + kk1.x), a00);
            a01 = fmaf(vv.y, fast_tanh(q0v.y + kk1.y), a01);
            a10 = fmaf(vv.y, fast_tanh(q1v.y + kk1.x), a10);
            a11 = fmaf(vv.y, fast_tanh(q1v.y + kk1.y), a11);

            a00 = fmaf(vv.z, fast_tanh(q0v.z + kk2.x), a00);
            a01 = fmaf(vv.z, fast_tanh(q0v.z + kk2.y), a01);
            a10 = fmaf(vv.z, fast_tanh(q1v.z + kk2.x), a10);
            a11 = fmaf(vv.z, fast_tanh(q1v.z + kk2.y), a11);

            a00 = fmaf(vv.w, fast_tanh(q0v.w + kk3.x), a00);
            a01 = fmaf(vv.w, fast_tanh(q0v.w + kk3.y), a01);
            a10 = fmaf(vv.w, fast_tanh(q1v.w + kk3.x), a10);
            a11 = fmaf(vv.w, fast_tanh(q1v.w + kk3.y), a11);
        }
        __syncthreads();
    }

    {
        float2 o0; o0.x = a00; o0.y = a01;
        float2 o1; o1.x = a10; o1.y = a11;
        *(float2*)&out[((size_t)b * NQ + q0 + tq * 2 + 0) * NK + k0 + tk * 2] = o0;
        *(float2*)&out[((size_t)b * NQ + q0 + tq * 2 + 1) * NK + k0 + tk * 2] = o1;
    }
}

extern "C" void kernel_launch(void* const* d_in, const int* in_sizes, int n_in,
                              void* d_out, int out_size)
{
    const float* query = (const float*)d_in[0];  // [8,128,512]
    const float* key   = (const float*)d_in[1];  // [8,256,512]
    const float* W1    = (const float*)d_in[2];  // [512,512]
    const float* b1    = (const float*)d_in[3];  // [512]
    const float* W2    = (const float*)d_in[4];  // [512,512]
    const float* b2    = (const float*)d_in[5];  // [512]
    const float* v     = (const float*)d_in[6];  // [512]
    float* out = (float*)d_out;                  // [8,128,256]

    convert_kernel<<<1024, 256>>>((const float4*)query, (const float4*)key,
                                  (const float4*)W1, (const float4*)W2);
    // 48 m-tiles (3072/64) x 8 n-tiles (512/64) = 384 blocks
    proj_mma<<<dim3(48, 8), 128>>>(b1, b2);
    // 8 k-tiles x 8 q-tiles x 8 batches = 512 blocks
    score_kernel<<<dim3(NK / SK, NQ / SQ, NB), 128>>>(v, out);
}